// round 17
// baseline (speedup 1.0000x reference)
#include <cuda_runtime.h>
#include <cuda_fp16.h>
#include <math.h>
#include <stdint.h>

#define B_  4
#define S_  2048
#define H_  1024
#define NH_ 16
#define HD_ 64
#define M_  (B_ * S_)
#define SCALE_INV 0.125f

// Scratch (device globals — no allocation allowed)
__device__ __half g_Qh[M_ * H_];          // [B,NH,S,HD] half, pre-scaled 1/8
__device__ __half g_Kh[M_ * H_];          // [B,NH,S,HD] half
__device__ __half g_Vt[M_ * H_];          // [B,NH,HD,S] half (TRANSPOSED)
__device__ float  g_X[M_ * H_];           // [B,S,H] fp32
__device__ float  g_psum[64 * S_ * 32];   // [bh][q][kblock(64)] partial row sums
__device__ __half g_Ph[(size_t)64 * S_ * S_];  // unnormalized P, fp16

// ---------------------------------------------------------------------------
__device__ __forceinline__ uint32_t f2tf32(float x) {
    uint32_t r; asm("cvt.rna.tf32.f32 %0, %1;" : "=r"(r) : "f"(x)); return r;
}

__device__ __forceinline__ void mma_tf32(float* c, const uint32_t* a, const uint32_t* b) {
    asm volatile("mma.sync.aligned.m16n8k8.row.col.f32.tf32.tf32.f32 "
        "{%0,%1,%2,%3}, {%4,%5,%6,%7}, {%8,%9}, {%0,%1,%2,%3};"
        : "+f"(c[0]), "+f"(c[1]), "+f"(c[2]), "+f"(c[3])
        : "r"(a[0]), "r"(a[1]), "r"(a[2]), "r"(a[3]), "r"(b[0]), "r"(b[1]));
}
__device__ __forceinline__ void mma_f16(float* c, const uint32_t* a, const uint32_t* b) {
    asm volatile("mma.sync.aligned.m16n8k16.row.col.f32.f16.f16.f32 "
        "{%0,%1,%2,%3}, {%4,%5,%6,%7}, {%8,%9}, {%0,%1,%2,%3};"
        : "+f"(c[0]), "+f"(c[1]), "+f"(c[2]), "+f"(c[3])
        : "r"(a[0]), "r"(a[1]), "r"(a[2]), "r"(a[3]), "r"(b[0]), "r"(b[1]));
}

// tf32 fragment loaders (proj path, fp32 SMEM)
__device__ __forceinline__ void lda_frag(uint32_t* a, const float* s, int lds,
                                         int mbase, int k, int lane) {
    const float* p = s + (size_t)(mbase + (lane >> 2)) * lds + k + (lane & 3);
    a[0] = __float_as_uint(p[0]);
    a[1] = __float_as_uint(p[8 * lds]);
    a[2] = __float_as_uint(p[4]);
    a[3] = __float_as_uint(p[8 * lds + 4]);
}
__device__ __forceinline__ void ldb_frag(uint32_t* b, const float* s, int lds,
                                         int nbase, int k, int lane) {
    const float* p = s + (size_t)(nbase + (lane >> 2)) * lds + k + (lane & 3);
    b[0] = __float_as_uint(p[0]);
    b[1] = __float_as_uint(p[4]);
}
// fp16 fragment loaders (half SMEM; k-pairs contiguous -> 32-bit LDS)
__device__ __forceinline__ void lda_f16(uint32_t* a, const __half* s, int lds,
                                        int mbase, int koff, int lane) {
    const __half* p = s + (size_t)(mbase + (lane >> 2)) * lds + koff + (lane & 3) * 2;
    a[0] = *(const uint32_t*)p;
    a[1] = *(const uint32_t*)(p + 8 * lds);
    a[2] = *(const uint32_t*)(p + 8);
    a[3] = *(const uint32_t*)(p + 8 * lds + 8);
}
__device__ __forceinline__ void ldb_f16(uint32_t* b, const __half* s, int lds,
                                        int nbase, int koff, int lane) {
    const __half* p = s + (size_t)(nbase + (lane >> 2)) * lds + koff + (lane & 3) * 2;
    b[0] = *(const uint32_t*)p;
    b[1] = *(const uint32_t*)(p + 8);
}

__device__ __forceinline__ uint32_t smaddr(const void* p) {
    return (uint32_t)__cvta_generic_to_shared(p);
}
#define CP_ASYNC16(dst, src) \
    asm volatile("cp.async.cg.shared.global [%0], [%1], 16;" :: "r"(dst), "l"(src))
#define CP_COMMIT() asm volatile("cp.async.commit_group;" ::: "memory")
#define CP_WAIT0()  asm volatile("cp.async.wait_group 0;" ::: "memory")
#define CP_WAIT1()  asm volatile("cp.async.wait_group 1;" ::: "memory")

// ---------------------------------------------------------------------------
// Projection GEMM body (R7 tf32 mainloop — best measured).
// mode 0: fp32 out[m][n]
// mode 2: half out[b,h,s,d] * 1/8  (Q)
// mode 3: half out[b,h,s,d]        (K)
// mode 4: half out[b,h,d,s]        (V transposed)
// ---------------------------------------------------------------------------
__device__ __forceinline__ void proj_body(const float* __restrict__ A,
                                          const float* __restrict__ W,
                                          const float* __restrict__ bias,
                                          void* __restrict__ outv, int mode,
                                          float (*sA)[128][36], float (*sB)[128][36]) {
    const int tid = threadIdx.x, lane = tid & 31, w = tid >> 5;
    const int wm = (w >> 2) * 64, wn = (w & 3) * 32;
    const int m0 = blockIdx.y * 128, n0 = blockIdx.x * 128;

    float acc[4][4][4] = {};

    #pragma unroll
    for (int i = tid; i < 1024; i += 256) {
        int r = i >> 3, c4 = (i & 7) * 4;
        CP_ASYNC16(smaddr(&sA[0][r][c4]), &A[(size_t)(m0 + r) * H_ + c4]);
        CP_ASYNC16(smaddr(&sB[0][r][c4]), &W[(size_t)(n0 + r) * H_ + c4]);
    }
    CP_COMMIT();

    for (int it = 0; it < 32; it++) {
        const int s = it & 1;
        if (it + 1 < 32) {
            const int kn = (it + 1) * 32, sn = s ^ 1;
            #pragma unroll
            for (int i = tid; i < 1024; i += 256) {
                int r = i >> 3, c4 = (i & 7) * 4;
                CP_ASYNC16(smaddr(&sA[sn][r][c4]), &A[(size_t)(m0 + r) * H_ + kn + c4]);
                CP_ASYNC16(smaddr(&sB[sn][r][c4]), &W[(size_t)(n0 + r) * H_ + kn + c4]);
            }
            CP_COMMIT();
            CP_WAIT1();
        } else {
            CP_WAIT0();
        }
        __syncthreads();

        #pragma unroll
        for (int ks = 0; ks < 4; ks++) {
            uint32_t af[4][4], bf[4][2];
            #pragma unroll
            for (int mt = 0; mt < 4; mt++) {
                lda_frag(af[mt], &sA[s][0][0], 36, wm + mt * 16, ks * 8, lane);
                #pragma unroll
                for (int j = 0; j < 4; j++) af[mt][j] = f2tf32(__uint_as_float(af[mt][j]));
            }
            #pragma unroll
            for (int nt = 0; nt < 4; nt++) {
                ldb_frag(bf[nt], &sB[s][0][0], 36, wn + nt * 8, ks * 8, lane);
                bf[nt][0] = f2tf32(__uint_as_float(bf[nt][0]));
                bf[nt][1] = f2tf32(__uint_as_float(bf[nt][1]));
            }
            #pragma unroll
            for (int mt = 0; mt < 4; mt++)
                #pragma unroll
                for (int nt = 0; nt < 4; nt++)
                    mma_tf32(acc[mt][nt], af[mt], bf[nt]);
        }
        __syncthreads();
    }

    #pragma unroll
    for (int mt = 0; mt < 4; mt++) {
        #pragma unroll
        for (int nt = 0; nt < 4; nt++) {
            int r0 = m0 + wm + mt * 16 + (lane >> 2);
            int c0 = n0 + wn + nt * 8 + (lane & 3) * 2;
            #pragma unroll
            for (int e = 0; e < 4; e++) {
                int m = r0 + (e >> 1) * 8;
                int n = c0 + (e & 1);
                float v = acc[mt][nt][e] + bias[n];
                if (mode == 0) {
                    ((float*)outv)[(size_t)m * H_ + n] = v;
                } else {
                    int b = m >> 11, sq = m & 2047, h = n >> 6, dd = n & 63;
                    __half* o = (__half*)outv;
                    if (mode == 2)
                        o[(((size_t)(b * NH_ + h) * S_) + sq) * HD_ + dd] =
                            __float2half_rn(v * SCALE_INV);
                    else if (mode == 3)
                        o[(((size_t)(b * NH_ + h) * S_) + sq) * HD_ + dd] =
                            __float2half_rn(v);
                    else  // mode 4: V transposed
                        o[(((size_t)(b * NH_ + h) * HD_) + dd) * S_ + sq] =
                            __float2half_rn(v);
                }
            }
        }
    }
}

__global__ __launch_bounds__(256, 2) void proj_mma(const float* __restrict__ A,
                                                   const float* __restrict__ W,
                                                   const float* __restrict__ bias,
                                                   void* __restrict__ out, int mode) {
    __shared__ float sA[2][128][36];
    __shared__ float sB[2][128][36];
    proj_body(A, W, bias, out, mode, sA, sB);
}

// Fused Q+K projection: blockIdx.z selects operand set.
__global__ __launch_bounds__(256, 2) void proj_qk(const float* __restrict__ q,
                                                  const float* __restrict__ kk,
                                                  const float* __restrict__ Wq,
                                                  const float* __restrict__ Wk,
                                                  const float* __restrict__ bq,
                                                  const float* __restrict__ bk,
                                                  __half* __restrict__ oq,
                                                  __half* __restrict__ ok) {
    __shared__ float sA[2][128][36];
    __shared__ float sB[2][128][36];
    if (blockIdx.z == 0)
        proj_body(q, Wq, bq, oq, 2, sA, sB);     // Q: half * 1/8
    else
        proj_body(kk, Wk, bk, ok, 3, sA, sB);    // K: half
}

// ---------------------------------------------------------------------------
// Energy + exp + mask, fp16 MMA. Tile 128(q) x 64(k), K=HD=64 -> 4 ksteps.
// Q/K tiles are half (bytes halved). Writes fp16 unnormalized P + psum.
// ---------------------------------------------------------------------------
__global__ __launch_bounds__(256, 3) void energy_exp(const int* __restrict__ mask,
                                                     __half* __restrict__ ph,
                                                     float* __restrict__ psum) {
    __shared__ union {
        struct { __half A[128][72]; __half B[64][72]; } ld;
        float E[128][68];
    } sm;
    const int tid = threadIdx.x, lane = tid & 31, w = tid >> 5;
    const int wm = (w >> 1) * 32, wn = (w & 1) * 32;
    const int bh = blockIdx.z, b = bh >> 4;
    const int q0 = blockIdx.y * 128, k0 = blockIdx.x * 64;
    const int kblk = blockIdx.x;
    const __half* Qb = g_Qh + (size_t)bh * S_ * HD_;
    const __half* Kb = g_Kh + (size_t)bh * S_ * HD_;

    // Tile loads: Q 128x64 half (128B/row = 8x16B), K 64x64 half.
    #pragma unroll
    for (int i = tid; i < 1024; i += 256) {
        int r = i >> 3, c8 = (i & 7) * 8;
        CP_ASYNC16(smaddr(&sm.ld.A[r][c8]), &Qb[(size_t)(q0 + r) * HD_ + c8]);
    }
    #pragma unroll
    for (int i = tid; i < 512; i += 256) {
        int r = i >> 3, c8 = (i & 7) * 8;
        CP_ASYNC16(smaddr(&sm.ld.B[r][c8]), &Kb[(size_t)(k0 + r) * HD_ + c8]);
    }
    CP_COMMIT();

    const int* mb = mask + (size_t)b * S_ * S_;
    const int cl = (tid & 15) * 4;
    const int k = k0 + cl;
    uint32_t pmask = 0;
    #pragma unroll
    for (int j = 0; j < 8; j++) {
        int q = q0 + j * 16 + (tid >> 4);
        int4 mv = *(const int4*)&mb[(size_t)q * S_ + k];
        uint32_t bits = (mv.x ? 1u : 0u) | (mv.y ? 2u : 0u)
                      | (mv.z ? 4u : 0u) | (mv.w ? 8u : 0u);
        pmask |= bits << (4 * j);
    }

    CP_WAIT0();
    __syncthreads();

    float acc[2][4][4] = {};
    #pragma unroll
    for (int ks = 0; ks < 4; ks++) {          // K=64, 16 per MMA
        uint32_t af[2][4], bf[4][2];
        #pragma unroll
        for (int mt = 0; mt < 2; mt++)
            lda_f16(af[mt], &sm.ld.A[0][0], 72, wm + mt * 16, ks * 16, lane);
        #pragma unroll
        for (int nt = 0; nt < 4; nt++)
            ldb_f16(bf[nt], &sm.ld.B[0][0], 72, wn + nt * 8, ks * 16, lane);
        #pragma unroll
        for (int mt = 0; mt < 2; mt++)
            #pragma unroll
            for (int nt = 0; nt < 4; nt++)
                mma_f16(acc[mt][nt], af[mt], bf[nt]);
    }
    __syncthreads();   // all warps done reading Q/K before E overwrites

    #pragma unroll
    for (int mt = 0; mt < 2; mt++) {
        int r = wm + mt * 16 + (lane >> 2);
        #pragma unroll
        for (int nt = 0; nt < 4; nt++) {
            int lc = wn + nt * 8 + (lane & 3) * 2;
            sm.E[r][lc]         = acc[mt][nt][0];
            sm.E[r][lc + 1]     = acc[mt][nt][1];
            sm.E[r + 8][lc]     = acc[mt][nt][2];
            sm.E[r + 8][lc + 1] = acc[mt][nt][3];
        }
    }
    __syncthreads();

    __half* pb = ph + (size_t)bh * S_ * S_;
    #pragma unroll
    for (int j = 0; j < 8; j++) {
        int row = j * 16 + (tid >> 4);
        int q = q0 + row;
        float4 ev = *(float4*)&sm.E[row][cl];
        uint32_t bits = (pmask >> (4 * j)) & 0xfu;
        __half h0 = (bits & 1u) ? __float2half_rn(__expf(ev.x)) : __half(0.f);
        __half h1 = (bits & 2u) ? __float2half_rn(__expf(ev.y)) : __half(0.f);
        __half h2 = (bits & 4u) ? __float2half_rn(__expf(ev.z)) : __half(0.f);
        __half h3 = (bits & 8u) ? __float2half_rn(__expf(ev.w)) : __half(0.f);
        __half2 h01 = __halves2half2(h0, h1);
        __half2 h23 = __halves2half2(h2, h3);
        uint2 pk = { *(uint32_t*)&h01, *(uint32_t*)&h23 };
        *(uint2*)&pb[(size_t)q * S_ + k] = pk;
        float v = (__half2float(h0) + __half2float(h1))
                + (__half2float(h2) + __half2float(h3));
        v += __shfl_xor_sync(0xffffffffu, v, 1);
        v += __shfl_xor_sync(0xffffffffu, v, 2);
        v += __shfl_xor_sync(0xffffffffu, v, 4);
        v += __shfl_xor_sync(0xffffffffu, v, 8);
        if ((tid & 15) == 0)
            psum[((size_t)bh * S_ + q) * 32 + kblk] = v;
    }
}

// ---------------------------------------------------------------------------
// PV + normalize, fp16 MMA. Tile 128(q) x 64(d), K chunked by 32 (2 ksteps).
// P and Vt (transposed, [d][s]) cp.async'd as half — zero cvt in the feed.
// Normalized fp32 attn written from staged halves; X normalized fp32.
// ---------------------------------------------------------------------------
__global__ __launch_bounds__(256, 3) void pv_norm(const __half* __restrict__ ph,
                                                  float* __restrict__ attn,
                                                  const float* __restrict__ psum) {
    __shared__ __half sP[2][128][40];
    __shared__ __half sVt[2][64][40];
    __shared__ float sInv[128];
    const int tid = threadIdx.x, lane = tid & 31, w = tid >> 5;
    const int wm = (w >> 1) * 32, wn = (w & 1) * 32;
    const int bh = blockIdx.y, b = bh >> 4, h = bh & 15;
    const int q0 = blockIdx.x * 128;
    const __half* Phb = ph + (size_t)bh * S_ * S_;
    float* Ab = attn + (size_t)bh * S_ * S_;
    const __half* Vtb = g_Vt + (size_t)bh * HD_ * S_;

    if (tid < 128) {
        const float* ps = psum + ((size_t)bh * S_ + q0 + tid) * 32;
        float sum = 0.f;
        #pragma unroll
        for (int i = 0; i < 32; i++) sum += ps[i];
        sInv[tid] = 1.0f / sum;
    }

    // Prefetch chunk 0: P 128x32 half (64B/row = 4x16B), Vt 64x32 half.
    #pragma unroll
    for (int i = tid; i < 512; i += 256) {
        int r = i >> 2, c8 = (i & 3) * 8;
        CP_ASYNC16(smaddr(&sP[0][r][c8]), &Phb[(size_t)(q0 + r) * S_ + c8]);
    }
    #pragma unroll
    for (int i = tid; i < 256; i += 256) {
        int r = i >> 2, c8 = (i & 3) * 8;
        CP_ASYNC16(smaddr(&sVt[0][r][c8]), &Vtb[(size_t)r * S_ + c8]);
    }
    CP_COMMIT();

    float acc[2][4][4] = {};

    for (int it = 0; it < 64; it++) {
        const int kc = it * 32, s = it & 1;
        if (it + 1 < 64) {
            const int kn = kc + 32, sn = s ^ 1;
            #pragma unroll
            for (int i = tid; i < 512; i += 256) {
                int r = i >> 2, c8 = (i & 3) * 8;
                CP_ASYNC16(smaddr(&sP[sn][r][c8]), &Phb[(size_t)(q0 + r) * S_ + kn + c8]);
            }
            #pragma unroll
            for (int i = tid; i < 256; i += 256) {
                int r = i >> 2, c8 = (i & 3) * 8;
                CP_ASYNC16(smaddr(&sVt[sn][r][c8]), &Vtb[(size_t)r * S_ + kn + c8]);
            }
            CP_COMMIT();
            CP_WAIT1();
        } else {
            CP_WAIT0();
        }
        __syncthreads();

        #pragma unroll
        for (int ks = 0; ks < 2; ks++) {      // chunk 32, 16 per MMA
            uint32_t af[2][4], bf[4][2];
            #pragma unroll
            for (int mt = 0; mt < 2; mt++)
                lda_f16(af[mt], &sP[s][0][0], 40, wm + mt * 16, ks * 16, lane);
            #pragma unroll
            for (int nt = 0; nt < 4; nt++)
                ldb_f16(bf[nt], &sVt[s][0][0], 40, wn + nt * 8, ks * 16, lane);
            #pragma unroll
            for (int mt = 0; mt < 2; mt++)
                #pragma unroll
                for (int nt = 0; nt < 4; nt++)
                    mma_f16(acc[mt][nt], af[mt], bf[nt]);
        }

        // Normalized fp32 attention store from the staged half tile.
        {
            const int r = tid >> 1, c0 = (tid & 1) * 16;
            float inv = sInv[r];
            const __half2* hp = (const __half2*)&sP[s][r][c0];
            float* dst = &Ab[(size_t)(q0 + r) * S_ + kc + c0];
            #pragma unroll
            for (int t = 0; t < 4; t++) {
                float2 f0 = __half22float2(hp[t * 2]);
                float2 f1 = __half22float2(hp[t * 2 + 1]);
                float4 o = { f0.x * inv, f0.y * inv, f1.x * inv, f1.y * inv };
                *(float4*)(dst + t * 4) = o;
            }
        }
        __syncthreads();
    }

    #pragma unroll
    for (int mt = 0; mt < 2; mt++) {
        #pragma unroll
        for (int nt = 0; nt < 4; nt++) {
            int rr = wm + mt * 16 + (lane >> 2);
            int c0 = wn + nt * 8 + (lane & 3) * 2;
            #pragma unroll
            for (int e = 0; e < 4; e++) {
                int rl = rr + (e >> 1) * 8;
                int q = q0 + rl;
                int d = c0 + (e & 1);
                g_X[((size_t)(b * S_ + q)) * H_ + h * HD_ + d] = acc[mt][nt][e] * sInv[rl];
            }
        }
    }
}

// ---------------------------------------------------------------------------
extern "C" void kernel_launch(void* const* d_in, const int* in_sizes, int n_in,
                              void* d_out, int out_size) {
    const float* query = (const float*)d_in[0];
    const float* key   = (const float*)d_in[1];
    const float* value = (const float*)d_in[2];
    const int*   mask  = (const int*)d_in[3];
    const float* Wq = (const float*)d_in[4];  const float* bq = (const float*)d_in[5];
    const float* Wk = (const float*)d_in[6];  const float* bk = (const float*)d_in[7];
    const float* Wv = (const float*)d_in[8];  const float* bv = (const float*)d_in[9];
    const float* Wo = (const float*)d_in[10]; const float* bo = (const float*)d_in[11];

    float* out  = (float*)d_out;
    float* attn = out + (size_t)B_ * S_ * H_;

    float *gX, *gPS;
    __half *gQh, *gKh, *gVt, *gPh;
    cudaGetSymbolAddress((void**)&gQh, g_Qh);
    cudaGetSymbolAddress((void**)&gKh, g_Kh);
    cudaGetSymbolAddress((void**)&gVt, g_Vt);
    cudaGetSymbolAddress((void**)&gX, g_X);
    cudaGetSymbolAddress((void**)&gPS, g_psum);
    cudaGetSymbolAddress((void**)&gPh, g_Ph);

    // Side stream for the V projection (independent of energy).
    cudaStream_t s1;
    cudaEvent_t e0, e1;
    cudaStreamCreateWithFlags(&s1, cudaStreamNonBlocking);
    cudaEventCreateWithFlags(&e0, cudaEventDisableTiming);
    cudaEventCreateWithFlags(&e1, cudaEventDisableTiming);

    dim3 grid_proj(H_ / 128, M_ / 128);        // (8, 64)

    // Fork: V projection (half, transposed) overlaps QK proj + energy.
    cudaEventRecord(e0, 0);
    cudaStreamWaitEvent(s1, e0, 0);
    proj_mma<<<grid_proj, 256, 0, s1>>>(value, Wv, bv, gVt, 4);
    cudaEventRecord(e1, s1);

    // Main stream: fused Q+K projection.
    dim3 grid_qk(H_ / 128, M_ / 128, 2);       // (8, 64, 2)
    proj_qk<<<grid_qk, 256>>>(query, key, Wq, Wk, bq, bk, gQh, gKh);

    dim3 grid_e(S_ / 64, S_ / 128, B_ * NH_);  // (32, 16, 64)
    energy_exp<<<grid_e, 256>>>(mask, gPh, gPS);

    // Join: pv needs g_Vt.
    cudaStreamWaitEvent(0, e1, 0);

    dim3 grid_pv(S_ / 128, B_ * NH_);          // (16, 64)
    pv_norm<<<grid_pv, 256>>>(gPh, attn, gPS);

    proj_mma<<<grid_proj, 256>>>(gX, Wo, bo, out, 0);
}